// round 2
// baseline (speedup 1.0000x reference)
#include <cuda_runtime.h>
#include <math.h>

// Problem constants: N=8, S=8192, C=1, K=1024, V=64
#define NS_TOTAL 65536
#define VDIM 64
#define KCW 1024
#define BM 128
#define BK 128
#define NCHUNK (KCW / BK)

#define XS_STRIDE 258            // 2*BM + 2 floats (duplicated x pairs, padded)
#define ES_STRIDE 130            // BK + 2 floats (padded)
#define XS_FLOATS (VDIM * XS_STRIDE)   // 16512
#define ES_FLOATS (VDIM * ES_STRIDE)   // 8320
#define SMEM_FLOATS (XS_FLOATS + ES_FLOATS + BM)   // + xn row norms
#define SMEM_BYTES (SMEM_FLOATS * 4)               // 99840 B

__device__ float g_en[KCW];
__device__ int   g_counts[KCW];

// Packed fp32x2 FMA (Blackwell sm_100+/sm_103a; PTX-only form).
// IEEE round-to-nearest per 32-bit lane == scalar fmaf chain bit-for-bit.
__device__ __forceinline__ unsigned long long ffma2(unsigned long long a,
                                                    unsigned long long b,
                                                    unsigned long long c) {
    unsigned long long d;
    asm("fma.rn.f32x2 %0, %1, %2, %3;" : "=l"(d) : "l"(a), "l"(b), "l"(c));
    return d;
}

__device__ __forceinline__ void unpack2(unsigned long long v, float& lo, float& hi) {
    unsigned int l, h;
    asm("mov.b64 {%0, %1}, %2;" : "=r"(l), "=r"(h) : "l"(v));
    lo = __uint_as_float(l);
    hi = __uint_as_float(h);
}

// ---------------------------------------------------------------------------
// Kernel 1: codeword squared norms (sequential mul+add, v ascending — matches
// XLA:CPU fusion-loop reduction semantics: no FMA, no reassociation) + zero hist
// ---------------------------------------------------------------------------
__global__ void vq_prep_kernel(const float* __restrict__ emb) {
    int k = blockIdx.x * blockDim.x + threadIdx.x;   // 0..1023
    if (k < KCW) {
        float acc = 0.0f;
        const float* e = emb + (size_t)k * VDIM;
        #pragma unroll 8
        for (int v = 0; v < VDIM; v++)
            acc = __fadd_rn(acc, __fmul_rn(e[v], e[v]));
        g_en[k]     = acc;
        g_counts[k] = 0;
    }
}

// ---------------------------------------------------------------------------
// Kernel 2: main fused GEMM + argmin + histogram + outputs
// grid 512 blocks (128 samples each), 256 threads, 2 CTAs/SM
// ---------------------------------------------------------------------------
__global__ __launch_bounds__(256, 2)
void vq_main_kernel(const float* __restrict__ x, const float* __restrict__ emb,
                    float* __restrict__ out0, float* __restrict__ out1,
                    float* __restrict__ out2) {
    extern __shared__ float sm[];
    float* xs2  = sm;                      // [VDIM][XS_STRIDE] duplicated x pairs
    float* es   = sm + XS_FLOATS;          // [VDIM][ES_STRIDE] e chunk (transposed)
    float* xn_s = sm + XS_FLOATS + ES_FLOATS;   // [BM] row ||x||^2
    // after the compute loop, the es region is reused:
    float* red_val = es;                   // [16][ES_STRIDE]
    int*   red_idx = (int*)(es + 2080);    // [16][ES_STRIDE]
    int*   amin_s  = (int*)(es + 4160);    // [BM]
    float* rowsum  = es + 4288;            // [BM]

    const int tid  = threadIdx.x;
    const int tx   = tid & 15;
    const int ty   = tid >> 4;
    const int row0 = blockIdx.x * BM;

    // ---- load x tile (coalesced float4), store duplicated (v-major) ----
    const float4* x4 = reinterpret_cast<const float4*>(x) + (size_t)row0 * (VDIM / 4);
    #pragma unroll
    for (int t = 0; t < 8; t++) {
        int lin4 = tid + t * 256;          // 2048 float4 total
        int r    = lin4 >> 4;
        int v4   = lin4 & 15;
        float4 val = x4[lin4];
        *reinterpret_cast<float2*>(xs2 + (v4 * 4 + 0) * XS_STRIDE + 2 * r) = make_float2(val.x, val.x);
        *reinterpret_cast<float2*>(xs2 + (v4 * 4 + 1) * XS_STRIDE + 2 * r) = make_float2(val.y, val.y);
        *reinterpret_cast<float2*>(xs2 + (v4 * 4 + 2) * XS_STRIDE + 2 * r) = make_float2(val.z, val.z);
        *reinterpret_cast<float2*>(xs2 + (v4 * 4 + 3) * XS_STRIDE + 2 * r) = make_float2(val.w, val.w);
    }
    __syncthreads();

    // ---- row norms ||x_r||^2: sequential mul+add, v ascending (XLA semantics) ----
    if (tid < BM) {
        float acc = 0.0f;
        const float* xr = xs2 + 2 * tid;
        #pragma unroll 8
        for (int v = 0; v < VDIM; v++) {
            float xv = xr[v * XS_STRIDE];
            acc = __fadd_rn(acc, __fmul_rn(xv, xv));
        }
        xn_s[tid] = acc;
    }

    float minv[8];
    int   mini[8];
    #pragma unroll
    for (int i = 0; i < 8; i++) { minv[i] = 3.402823466e38f; mini[i] = 0; }

    // thread covers rows r_i = ty + 16*i, codewords k = c*128 + 32*m + 2*tx + {0,1}
    for (int c = 0; c < NCHUNK; c++) {
        if (c > 0) __syncthreads();   // previous chunk's compute done before overwriting es
        const float4* e4 = reinterpret_cast<const float4*>(emb) + (size_t)c * (BK * VDIM / 4);
        #pragma unroll
        for (int t = 0; t < 8; t++) {
            int lin4 = tid + t * 256;
            int k    = lin4 >> 4;
            int v4   = lin4 & 15;
            float4 val = e4[lin4];
            es[(v4 * 4 + 0) * ES_STRIDE + k] = val.x;
            es[(v4 * 4 + 1) * ES_STRIDE + k] = val.y;
            es[(v4 * 4 + 2) * ES_STRIDE + k] = val.z;
            es[(v4 * 4 + 3) * ES_STRIDE + k] = val.w;
        }
        __syncthreads();

        unsigned long long acc[8][4];
        #pragma unroll
        for (int i = 0; i < 8; i++)
            #pragma unroll
            for (int m = 0; m < 4; m++) acc[i][m] = 0ULL;

        const float* xb = xs2 + 2 * ty;
        const float* eb = es + 2 * tx;
        // dot accumulation: sequential FMA over v=0..63, single accumulator
        // per (row, codeword) — matches Eigen gemm (FMA, k ascending).
        #pragma unroll 8
        for (int v = 0; v < VDIM; v++) {
            unsigned long long ep[4];
            #pragma unroll
            for (int m = 0; m < 4; m++)
                ep[m] = *reinterpret_cast<const unsigned long long*>(eb + v * ES_STRIDE + 32 * m);
            unsigned long long xp[8];
            #pragma unroll
            for (int i = 0; i < 8; i++)
                xp[i] = *reinterpret_cast<const unsigned long long*>(xb + v * XS_STRIDE + 32 * i);
            #pragma unroll
            for (int i = 0; i < 8; i++)
                #pragma unroll
                for (int m = 0; m < 4; m++)
                    acc[i][m] = ffma2(xp[i], ep[m], acc[i][m]);
        }

        // score = fl( fl( xn - fl(2*dot) ) + en )  — exact reference rounding
        float xnv[8];
        #pragma unroll
        for (int i = 0; i < 8; i++) xnv[i] = xn_s[ty + 16 * i];
        #pragma unroll
        for (int m = 0; m < 4; m++) {
            int k0 = c * BK + 32 * m + 2 * tx;
            float en0 = g_en[k0];
            float en1 = g_en[k0 + 1];
            #pragma unroll
            for (int i = 0; i < 8; i++) {
                float lo, hi;
                unpack2(acc[i][m], lo, hi);
                float s0 = __fadd_rn(__fsub_rn(xnv[i], __fmul_rn(2.0f, lo)), en0);
                float s1 = __fadd_rn(__fsub_rn(xnv[i], __fmul_rn(2.0f, hi)), en1);
                if (s0 < minv[i]) { minv[i] = s0; mini[i] = k0; }
                if (s1 < minv[i]) { minv[i] = s1; mini[i] = k0 + 1; }
            }
        }
    }

    // ---- cross-thread argmin reduction (16 candidates per row) ----
    __syncthreads();   // all compute reads of es done before aliasing writes
    #pragma unroll
    for (int i = 0; i < 8; i++) {
        int r = ty + 16 * i;
        red_val[tx * ES_STRIDE + r] = minv[i];
        red_idx[tx * ES_STRIDE + r] = mini[i];
    }
    __syncthreads();
    if (tid < BM) {
        int r = tid;
        float bv = red_val[r];
        int   bi = red_idx[r];
        #pragma unroll
        for (int j = 1; j < 16; j++) {
            float v  = red_val[j * ES_STRIDE + r];
            int   id = red_idx[j * ES_STRIDE + r];
            if (v < bv || (v == bv && id < bi)) { bv = v; bi = id; }
        }
        amin_s[r] = bi;
        rowsum[r] = 0.0f;
        atomicAdd(&g_counts[bi], 1);
    }
    __syncthreads();

    // ---- outputs: out0 = fl(fl(o - x) + x) (exact straight-through rounding),
    //               out1 = out2 = sum_v (x - o)^2 ----
    #pragma unroll 4
    for (int t = 0; t < 32; t++) {
        int i = t * 256 + tid;
        int r = i >> 6;
        int v = i & 63;
        float o  = emb[amin_s[r] * VDIM + v];      // all lanes same codeword: coalesced
        float xv = xs2[v * XS_STRIDE + 2 * r];
        float d  = __fsub_rn(xv, o);
        float sq = __fmul_rn(d, d);
        #pragma unroll
        for (int off = 16; off > 0; off >>= 1)
            sq += __shfl_down_sync(0xffffffffu, sq, off);
        if ((tid & 31) == 0) atomicAdd(&rowsum[r], sq);   // 2 adds/row: order-invariant
        out0[(size_t)(row0 + r) * VDIM + v] = __fadd_rn(__fsub_rn(o, xv), xv);
    }
    __syncthreads();
    if (tid < BM) {
        float s = rowsum[tid];
        out1[row0 + tid] = s;
        out2[row0 + tid] = s;
    }
}

// ---------------------------------------------------------------------------
// Kernel 3: entropy of the histogram
// ---------------------------------------------------------------------------
__global__ void vq_entropy_kernel(float* __restrict__ ent) {
    __shared__ float warpsum[32];
    int k = threadIdx.x;                   // 1024 threads
    int c = g_counts[k];
    float term = 0.0f;
    if (c > 0) {
        float p = (float)c * (1.0f / 65536.0f);   // exact (power-of-2 divisor)
        term = -p * logf(p);
    }
    #pragma unroll
    for (int off = 16; off > 0; off >>= 1)
        term += __shfl_down_sync(0xffffffffu, term, off);
    int lane = k & 31, wid = k >> 5;
    if (lane == 0) warpsum[wid] = term;
    __syncthreads();
    if (wid == 0) {
        float s = warpsum[lane];
        #pragma unroll
        for (int off = 16; off > 0; off >>= 1)
            s += __shfl_down_sync(0xffffffffu, s, off);
        if (lane == 0) *ent = s;
    }
}

// ---------------------------------------------------------------------------
extern "C" void kernel_launch(void* const* d_in, const int* in_sizes, int n_in,
                              void* d_out, int out_size) {
    const float* x;
    const float* emb;
    // identify inputs by size (x0 = 4194304, embedding0 = 65536)
    if (in_sizes[0] == NS_TOTAL * VDIM) {
        x   = (const float*)d_in[0];
        emb = (const float*)d_in[1];
    } else {
        x   = (const float*)d_in[1];
        emb = (const float*)d_in[0];
    }

    float* out0 = (float*)d_out;                        // 65536*64
    float* out1 = out0 + (size_t)NS_TOTAL * VDIM;       // 65536
    float* out2 = out1 + NS_TOTAL;                      // 65536
    float* ent  = out2 + NS_TOTAL;                      // 1

    cudaFuncSetAttribute(vq_main_kernel,
                         cudaFuncAttributeMaxDynamicSharedMemorySize, SMEM_BYTES);

    vq_prep_kernel<<<4, 256>>>(emb);
    vq_main_kernel<<<512, 256, SMEM_BYTES>>>(x, emb, out0, out1, out2);
    vq_entropy_kernel<<<1, 1024>>>(ent);
}

// round 3
// speedup vs baseline: 1.0153x; 1.0153x over previous
#include <cuda_runtime.h>
#include <math.h>

// Problem constants: N=8, S=8192, C=1, K=1024, V=64
#define NS_TOTAL 65536
#define VDIM 64
#define KCW 1024
#define BM 128
#define BK 256
#define NCHUNK (KCW / BK)      // 4

#define ST 258                 // float stride for both xs (2*BM+2) and es (BK+2)
#define XS_FLOATS (VDIM * ST)  // 16512
#define ES_FLOATS (VDIM * ST)  // 16512
#define SMEM_FLOATS (XS_FLOATS + ES_FLOATS + KCW + BM)
#define SMEM_BYTES (SMEM_FLOATS * 4)   // 136,704 B

typedef unsigned long long ull;

__device__ float g_en[KCW];
__device__ int   g_counts[KCW];

// Packed fp32x2 ops (Blackwell sm_103a; PTX-only forms). IEEE rn per 32-bit lane.
__device__ __forceinline__ ull ffma2(ull a, ull b, ull c) {
    ull d;
    asm("fma.rn.f32x2 %0, %1, %2, %3;" : "=l"(d) : "l"(a), "l"(b), "l"(c));
    return d;
}
__device__ __forceinline__ ull fmul2(ull a, ull b) {
    ull d;
    asm("mul.rn.f32x2 %0, %1, %2;" : "=l"(d) : "l"(a), "l"(b));
    return d;
}
__device__ __forceinline__ ull fadd2(ull a, ull b) {
    ull d;
    asm("add.rn.f32x2 %0, %1, %2;" : "=l"(d) : "l"(a), "l"(b));
    return d;
}
__device__ __forceinline__ void unpack2(ull v, float& lo, float& hi) {
    unsigned int l, h;
    asm("mov.b64 {%0, %1}, %2;" : "=r"(l), "=r"(h) : "l"(v));
    lo = __uint_as_float(l);
    hi = __uint_as_float(h);
}
__device__ __forceinline__ ull pack2(float lo, float hi) {
    ull v;
    asm("mov.b64 %0, {%1, %2};" : "=l"(v) : "f"(lo), "f"(hi));
    return v;
}

// e-tile bank swizzle: float-index idx -> idx ^ (4*((v>>2)&7)).
// Touches float-idx bits [2..4] only: keeps ull pair adjacency/alignment and
// commutes with +32*m (bit5+). Turns 4-way STS conflicts into 2-way.
#define ESWZ(v) (4 * (((v) >> 2) & 7))

// ---------------------------------------------------------------------------
// Kernel 1: codeword norms (sequential mul+add, v ascending) + zero histogram
// ---------------------------------------------------------------------------
__global__ void vq_prep_kernel(const float* __restrict__ emb) {
    int k = blockIdx.x * blockDim.x + threadIdx.x;   // 0..1023
    if (k < KCW) {
        float acc = 0.0f;
        const float* e = emb + (size_t)k * VDIM;
        #pragma unroll 8
        for (int v = 0; v < VDIM; v++)
            acc = __fadd_rn(acc, __fmul_rn(e[v], e[v]));
        g_en[k]     = acc;
        g_counts[k] = 0;
    }
}

// ---------------------------------------------------------------------------
// Kernel 2: fused GEMM + argmin + histogram + outputs
// grid 512 (128 samples each), 256 threads, 1 CTA/SM (regs+smem)
// thread tile: 8 rows x 16 codewords (8 packed pairs)
// ---------------------------------------------------------------------------
__global__ __launch_bounds__(256, 1)
void vq_main_kernel(const float* __restrict__ x, const float* __restrict__ emb,
                    float* __restrict__ out0, float* __restrict__ out1,
                    float* __restrict__ out2) {
    extern __shared__ float sm[];
    float* xs2  = sm;                          // [VDIM][ST] duplicated x pairs
    float* es   = sm + XS_FLOATS;              // [VDIM][ST] e chunk (transposed, swizzled)
    float* en_s = sm + XS_FLOATS + ES_FLOATS;  // [KCW] codeword norms
    float* xn_s = en_s + KCW;                  // [BM] row norms
    // post-loop overlays on es:
    float* red_val = es;                       // [16][130]
    int*   red_idx = (int*)(es + 2080);
    int*   amin_s  = (int*)(es + 4160);
    float* rowsum  = es + 4288;

    const int tid  = threadIdx.x;
    const int tx   = tid & 15;                 // 16 codeword-pair groups
    const int ty   = tid >> 4;                 // 16 row groups
    const int row0 = blockIdx.x * BM;

    // ---- load x tile (coalesced float4), store duplicated pairs (v-major) ----
    const float4* x4 = reinterpret_cast<const float4*>(x) + (size_t)row0 * (VDIM / 4);
    #pragma unroll
    for (int t = 0; t < 8; t++) {
        int lin4 = tid + t * 256;              // 2048 float4
        int r    = lin4 >> 4;
        int v4   = lin4 & 15;
        float4 val = x4[lin4];
        *reinterpret_cast<float2*>(xs2 + (v4 * 4 + 0) * ST + 2 * r) = make_float2(val.x, val.x);
        *reinterpret_cast<float2*>(xs2 + (v4 * 4 + 1) * ST + 2 * r) = make_float2(val.y, val.y);
        *reinterpret_cast<float2*>(xs2 + (v4 * 4 + 2) * ST + 2 * r) = make_float2(val.z, val.z);
        *reinterpret_cast<float2*>(xs2 + (v4 * 4 + 3) * ST + 2 * r) = make_float2(val.w, val.w);
    }
    // ---- copy codeword norms into smem (4 per thread) ----
    #pragma unroll
    for (int t = 0; t < 4; t++) en_s[tid + t * 256] = g_en[tid + t * 256];
    __syncthreads();

    // ---- row norms ||x_r||^2 (sequential mul+add, v ascending) ----
    if (tid < BM) {
        float acc = 0.0f;
        const float* xr = xs2 + 2 * tid;
        #pragma unroll 8
        for (int v = 0; v < VDIM; v++) {
            float xv = xr[v * ST];
            acc = __fadd_rn(acc, __fmul_rn(xv, xv));
        }
        xn_s[tid] = acc;
    }

    float minv[8];
    int   mini[8];
    #pragma unroll
    for (int i = 0; i < 8; i++) { minv[i] = 3.402823466e38f; mini[i] = 0; }

    const ull NEG2 = 0xC0000000C0000000ULL;    // {-2.0f, -2.0f}

    // thread covers rows r_i = ty + 16*i (i<8), codewords k = c*256 + 32*m + 2*tx + {0,1} (m<8)
    for (int c = 0; c < NCHUNK; c++) {
        if (c > 0) __syncthreads();            // compute done before overwriting es
        const float4* e4 = reinterpret_cast<const float4*>(emb) + (size_t)c * (BK * VDIM / 4);
        #pragma unroll
        for (int t = 0; t < 16; t++) {
            int lin4 = tid + t * 256;          // 4096 float4
            int k    = lin4 >> 4;
            int v4   = lin4 & 15;
            float4 val = e4[lin4];
            int swz = 4 * (v4 & 7);            // ESWZ(4*v4+j) == ESWZ(4*v4)
            es[(((v4 * 4 + 0) * ST + k)) ^ swz] = val.x;
            es[(((v4 * 4 + 1) * ST + k)) ^ swz] = val.y;
            es[(((v4 * 4 + 2) * ST + k)) ^ swz] = val.z;
            es[(((v4 * 4 + 3) * ST + k)) ^ swz] = val.w;
        }
        __syncthreads();

        ull acc[8][8];
        #pragma unroll
        for (int i = 0; i < 8; i++)
            #pragma unroll
            for (int m = 0; m < 8; m++) acc[i][m] = 0ULL;

        const int txk = 2 * tx;
        const int tyk = 2 * ty;
        // sequential FMA over v=0..63, single accumulator per (row, codeword)
        #pragma unroll 8
        for (int v = 0; v < VDIM; v++) {
            int ei = (v * ST + txk) ^ ESWZ(v);
            ull ep[8];
            #pragma unroll
            for (int m = 0; m < 8; m++)
                ep[m] = *reinterpret_cast<const ull*>(es + ei + 32 * m);
            ull xp[8];
            #pragma unroll
            for (int i = 0; i < 8; i++)
                xp[i] = *reinterpret_cast<const ull*>(xs2 + v * ST + tyk + 32 * i);
            #pragma unroll
            for (int i = 0; i < 8; i++)
                #pragma unroll
                for (int m = 0; m < 8; m++)
                    acc[i][m] = ffma2(xp[i], ep[m], acc[i][m]);
        }

        // score = fl( fl( xn - fl(2*dot) ) + en ) via packed ops (exact per lane)
        ull xn2[8];
        #pragma unroll
        for (int i = 0; i < 8; i++) {
            float xnv = xn_s[ty + 16 * i];
            xn2[i] = pack2(xnv, xnv);
        }
        #pragma unroll
        for (int m = 0; m < 8; m++) {
            int kk = 32 * m + txk;             // local codeword pair base
            int k0 = c * BK + kk;              // global
            ull en2 = *reinterpret_cast<const ull*>(en_s + k0);
            #pragma unroll
            for (int i = 0; i < 8; i++) {
                ull s2 = fadd2(fadd2(xn2[i], fmul2(acc[i][m], NEG2)), en2);
                float s0, s1;
                unpack2(s2, s0, s1);
                if (s0 < minv[i]) { minv[i] = s0; mini[i] = k0; }
                if (s1 < minv[i]) { minv[i] = s1; mini[i] = k0 + 1; }
            }
        }
    }

    // ---- cross-thread argmin reduction (16 candidates per row) ----
    __syncthreads();
    #pragma unroll
    for (int i = 0; i < 8; i++) {
        int r = ty + 16 * i;
        red_val[tx * 130 + r] = minv[i];
        red_idx[tx * 130 + r] = mini[i];
    }
    __syncthreads();
    if (tid < BM) {
        int r = tid;
        float bv = red_val[r];
        int   bi = red_idx[r];
        #pragma unroll
        for (int j = 1; j < 16; j++) {
            float v  = red_val[j * 130 + r];
            int   id = red_idx[j * 130 + r];
            if (v < bv || (v == bv && id < bi)) { bv = v; bi = id; }
        }
        amin_s[r] = bi;
        rowsum[r] = 0.0f;
        atomicAdd(&g_counts[bi], 1);
    }
    __syncthreads();

    // ---- outputs: out0 = fl(fl(o - x) + x), out1 = out2 = sum_v (x-o)^2 ----
    #pragma unroll 4
    for (int t = 0; t < 32; t++) {
        int i = t * 256 + tid;
        int r = i >> 6;
        int v = i & 63;
        float o  = emb[amin_s[r] * VDIM + v];
        float xv = xs2[v * ST + 2 * r];
        float d  = __fsub_rn(xv, o);
        float sq = __fmul_rn(d, d);
        #pragma unroll
        for (int off = 16; off > 0; off >>= 1)
            sq += __shfl_down_sync(0xffffffffu, sq, off);
        if ((tid & 31) == 0) atomicAdd(&rowsum[r], sq);   // 2 adds/row: order-invariant
        out0[(size_t)(row0 + r) * VDIM + v] = __fadd_rn(__fsub_rn(o, xv), xv);
    }
    __syncthreads();
    if (tid < BM) {
        float s = rowsum[tid];
        out1[row0 + tid] = s;
        out2[row0 + tid] = s;
    }
}

// ---------------------------------------------------------------------------
// Kernel 3: entropy of the histogram
// ---------------------------------------------------------------------------
__global__ void vq_entropy_kernel(float* __restrict__ ent) {
    __shared__ float warpsum[32];
    int k = threadIdx.x;                   // 1024 threads
    int c = g_counts[k];
    float term = 0.0f;
    if (c > 0) {
        float p = (float)c * (1.0f / 65536.0f);
        term = -p * logf(p);
    }
    #pragma unroll
    for (int off = 16; off > 0; off >>= 1)
        term += __shfl_down_sync(0xffffffffu, term, off);
    int lane = k & 31, wid = k >> 5;
    if (lane == 0) warpsum[wid] = term;
    __syncthreads();
    if (wid == 0) {
        float s = warpsum[lane];
        #pragma unroll
        for (int off = 16; off > 0; off >>= 1)
            s += __shfl_down_sync(0xffffffffu, s, off);
        if (lane == 0) *ent = s;
    }
}

// ---------------------------------------------------------------------------
extern "C" void kernel_launch(void* const* d_in, const int* in_sizes, int n_in,
                              void* d_out, int out_size) {
    const float* x;
    const float* emb;
    if (in_sizes[0] == NS_TOTAL * VDIM) {
        x   = (const float*)d_in[0];
        emb = (const float*)d_in[1];
    } else {
        x   = (const float*)d_in[1];
        emb = (const float*)d_in[0];
    }

    float* out0 = (float*)d_out;                        // 65536*64
    float* out1 = out0 + (size_t)NS_TOTAL * VDIM;       // 65536
    float* out2 = out1 + NS_TOTAL;                      // 65536
    float* ent  = out2 + NS_TOTAL;                      // 1

    cudaFuncSetAttribute(vq_main_kernel,
                         cudaFuncAttributeMaxDynamicSharedMemorySize, SMEM_BYTES);

    vq_prep_kernel<<<4, 256>>>(emb);
    vq_main_kernel<<<512, 256, SMEM_BYTES>>>(x, emb, out0, out1, out2);
    vq_entropy_kernel<<<1, 1024>>>(ent);
}